// round 5
// baseline (speedup 1.0000x reference)
#include <cuda_runtime.h>
#include <cstdint>
#include <math.h>

#define S_LEN   4096
#define DMODEL  768
#define NH      12
#define DH      64
#define QKV_LD  2304   // 3 * DMODEL
#define KDIM    768    // contraction dim for both projections

#define NEG_INF (__int_as_float(0xff800000))

// Scratch (allocation-free rule: __device__ globals)
__device__ float g_qkv[(size_t)S_LEN * QKV_LD];    // [4096, 2304]
__device__ float g_attn[(size_t)S_LEN * DMODEL];   // [4096, 768]

// ---------------------------------------------------------------------------
// helpers
// ---------------------------------------------------------------------------
__device__ __forceinline__ uint32_t f2tf32(float f) {
    uint32_t r;
    asm("cvt.rna.tf32.f32 %0, %1;" : "=r"(r) : "f"(f));
    return r;
}

__device__ __forceinline__ void mma_tf32(float* d, const uint32_t* a, const uint32_t* b) {
    asm volatile(
        "mma.sync.aligned.m16n8k8.row.col.f32.tf32.tf32.f32 "
        "{%0,%1,%2,%3}, {%4,%5,%6,%7}, {%8,%9}, {%0,%1,%2,%3};"
        : "+f"(d[0]), "+f"(d[1]), "+f"(d[2]), "+f"(d[3])
        : "r"(a[0]), "r"(a[1]), "r"(a[2]), "r"(a[3]), "r"(b[0]), "r"(b[1]));
}

__device__ __forceinline__ void cp16(void* dst, const void* src) {
    uint32_t d = (uint32_t)__cvta_generic_to_shared(dst);
    asm volatile("cp.async.cg.shared.global [%0], [%1], 16;\n" :: "r"(d), "l"(src));
}
#define CP_COMMIT() asm volatile("cp.async.commit_group;\n" ::: "memory")
#define CP_WAIT0()  asm volatile("cp.async.wait_group 0;\n" ::: "memory")

// ---------------------------------------------------------------------------
// C[M,N] = A[M,768] @ B[N,768]^T + bias[N]   tf32 tensor-core GEMM
// CTA 128x128, 8 warps (2x4), warp 64x32, K-step 32, cp.async double buffer.
// smem fp32, stride 36 (==4 mod 32) -> conflict-free fragment loads.
// ---------------------------------------------------------------------------
#define GSTR 36
#define KT_N (KDIM / 32)   // 24

__global__ __launch_bounds__(256, 2) void gemm_tf32(
    const float* __restrict__ A, const float* __restrict__ B,
    const float* __restrict__ bias, float* __restrict__ C, int N)
{
    extern __shared__ float smg[];
    float* As = smg;                   // [2][128*GSTR]
    float* Bs = smg + 2 * 128 * GSTR;  // [2][128*GSTR]

    const int t = threadIdx.x, lane = t & 31;
    const int w = t >> 5, wm = w >> 2, wn = w & 3;
    const int g = lane >> 2, tg = lane & 3;
    const int m0 = blockIdx.y * 128, n0 = blockIdx.x * 128;

    const int lrow = t >> 3, lc = (t & 7) * 4;  // 8 threads per 32-col row

    float acc[4][4][4] = {};

    // prologue: issue k-tile 0
#pragma unroll
    for (int i = 0; i < 4; i++) {
        int row = lrow + i * 32;
        cp16(&As[row * GSTR + lc], &A[(size_t)(m0 + row) * KDIM + lc]);
        cp16(&Bs[row * GSTR + lc], &B[(size_t)(n0 + row) * KDIM + lc]);
    }
    CP_COMMIT();

    for (int kt = 0; kt < KT_N; kt++) {
        CP_WAIT0();
        __syncthreads();
        if (kt + 1 < KT_N) {
            float* an = As + ((kt + 1) & 1) * 128 * GSTR;
            float* bn = Bs + ((kt + 1) & 1) * 128 * GSTR;
            const int ko = (kt + 1) * 32 + lc;
#pragma unroll
            for (int i = 0; i < 4; i++) {
                int row = lrow + i * 32;
                cp16(&an[row * GSTR + lc], &A[(size_t)(m0 + row) * KDIM + ko]);
                cp16(&bn[row * GSTR + lc], &B[(size_t)(n0 + row) * KDIM + ko]);
            }
            CP_COMMIT();
        }
        const float* ab = As + (kt & 1) * 128 * GSTR;
        const float* bb = Bs + (kt & 1) * 128 * GSTR;
#pragma unroll
        for (int kk = 0; kk < 4; kk++) {
            uint32_t afr[4][4], bfr[4][2];
#pragma unroll
            for (int mt = 0; mt < 4; mt++) {
                int r = wm * 64 + mt * 16 + g;
                afr[mt][0] = f2tf32(ab[r * GSTR + kk * 8 + tg]);
                afr[mt][1] = f2tf32(ab[(r + 8) * GSTR + kk * 8 + tg]);
                afr[mt][2] = f2tf32(ab[r * GSTR + kk * 8 + tg + 4]);
                afr[mt][3] = f2tf32(ab[(r + 8) * GSTR + kk * 8 + tg + 4]);
            }
#pragma unroll
            for (int nt = 0; nt < 4; nt++) {
                int c = wn * 32 + nt * 8 + g;
                bfr[nt][0] = f2tf32(bb[c * GSTR + kk * 8 + tg]);
                bfr[nt][1] = f2tf32(bb[c * GSTR + kk * 8 + tg + 4]);
            }
#pragma unroll
            for (int mt = 0; mt < 4; mt++)
#pragma unroll
                for (int nt = 0; nt < 4; nt++)
                    mma_tf32(acc[mt][nt], afr[mt], bfr[nt]);
        }
    }

    // epilogue: bias + store
#pragma unroll
    for (int nt = 0; nt < 4; nt++) {
        int cb = n0 + wn * 32 + nt * 8 + 2 * tg;
        float2 bv = *(const float2*)&bias[cb];
#pragma unroll
        for (int mt = 0; mt < 4; mt++) {
            int r = m0 + wm * 64 + mt * 16 + g;
            *(float2*)&C[(size_t)r * N + cb] =
                make_float2(acc[mt][nt][0] + bv.x, acc[mt][nt][1] + bv.y);
            *(float2*)&C[(size_t)(r + 8) * N + cb] =
                make_float2(acc[mt][nt][2] + bv.x, acc[mt][nt][3] + bv.y);
        }
    }
}

// ---------------------------------------------------------------------------
// Causal flash attention, tf32 tensor cores, cp.async double-buffered K/V.
// One CTA = (head, 128-row q tile). 8 warps, each owns 16 q rows.
// Bc = 64. Q fragments live in registers (staged once via Ps buffer).
// Warp-level n-tile skipping on diagonal tiles (ntlim).
// smem: Ps[128*68] tf32 + K[2][64*68] fp32 + V[2][64*72] fp32 = 106,496 B.
// ---------------------------------------------------------------------------
__global__ __launch_bounds__(256, 2) void attn_tf32(
    const float* __restrict__ qkv, float* __restrict__ out)
{
    extern __shared__ uint32_t sma[];
    uint32_t* Ps = sma;                       // [128][68] tf32 (Q staging first)
    float* Ks = (float*)(sma + 128 * 68);     // [2][64][68]
    float* Vs = Ks + 2 * 64 * 68;             // [2][64][72]

    const int qb = (int)(gridDim.x - 1) - (int)blockIdx.x;  // heavy tiles first
    const int h = blockIdx.y;
    const int q0 = qb * 128;
    const int t = threadIdx.x, lane = t & 31, w = t >> 5;
    const int g = lane >> 2, tg = lane & 3;
    const int rb = w * 16;

    const int lrow = t >> 4, lc = (t & 15) * 4;  // 16 threads per 64-col row
    const int jbmax = 2 * qb + 1;

    // prologue: issue K/V for jb=0
#pragma unroll
    for (int i = 0; i < 4; i++) {
        int row = lrow + i * 16;
        const float* bp = &qkv[(size_t)row * QKV_LD + h * DH + lc];
        cp16(&Ks[row * 68 + lc], bp + DMODEL);
        cp16(&Vs[row * 72 + lc], bp + 2 * DMODEL);
    }
    CP_COMMIT();

    // stage Q (fp32) in Ps region, then extract per-warp a-fragments to regs
    {
        float* Pf = (float*)Ps;
#pragma unroll
        for (int i = 0; i < 8; i++) {
            int row = lrow + i * 16;
            *(float4*)&Pf[row * 68 + lc] =
                *(const float4*)&qkv[(size_t)(q0 + row) * QKV_LD + h * DH + lc];
        }
    }
    __syncthreads();
    uint32_t qa[8][4];
    {
        const float* Pf = (const float*)Ps;
#pragma unroll
        for (int d8 = 0; d8 < 8; d8++) {
            qa[d8][0] = f2tf32(Pf[(rb + g) * 68 + d8 * 8 + tg]);
            qa[d8][1] = f2tf32(Pf[(rb + g + 8) * 68 + d8 * 8 + tg]);
            qa[d8][2] = f2tf32(Pf[(rb + g) * 68 + d8 * 8 + tg + 4]);
            qa[d8][3] = f2tf32(Pf[(rb + g + 8) * 68 + d8 * 8 + tg + 4]);
        }
    }

    float o[8][4] = {};
    float m0r = NEG_INF, m1r = NEG_INF;
    float l0r = 0.f, l1r = 0.f;
    const float sc = 0.125f;  // 1/sqrt(64)

    for (int jb = 0; jb <= jbmax; jb++) {
        CP_WAIT0();
        __syncthreads();   // group jb visible to all; prev compute done (buffers free)
        if (jb < jbmax) {
            float* kn = Ks + ((jb + 1) & 1) * 64 * 68;
            float* vn = Vs + ((jb + 1) & 1) * 64 * 72;
#pragma unroll
            for (int i = 0; i < 4; i++) {
                int row = lrow + i * 16;
                const float* bp = &qkv[(size_t)((jb + 1) * 64 + row) * QKV_LD + h * DH + lc];
                cp16(&kn[row * 68 + lc], bp + DMODEL);
                cp16(&vn[row * 72 + lc], bp + 2 * DMODEL);
            }
            CP_COMMIT();
        }

        // warp-level causal limit: active 8-col groups in this k-tile
        const int cmax = q0 + rb + 15 - jb * 64;
        if (cmax < 0) continue;                       // warp fully above diagonal
        const int ntlim = cmax >= 63 ? 8 : ((cmax >> 3) + 1);

        const float* kb = Ks + (jb & 1) * 64 * 68;
        const float* vb = Vs + (jb & 1) * 64 * 72;

        // S = Q @ K^T
        float sf[8][4] = {};
#pragma unroll
        for (int d8 = 0; d8 < 8; d8++) {
#pragma unroll
            for (int nt = 0; nt < 8; nt++) {
                if (nt >= ntlim) break;
                uint32_t b[2];
                b[0] = f2tf32(kb[(nt * 8 + g) * 68 + d8 * 8 + tg]);
                b[1] = f2tf32(kb[(nt * 8 + g) * 68 + d8 * 8 + tg + 4]);
                mma_tf32(sf[nt], qa[d8], b);
            }
        }

        // scale + causal mask
        const int row0 = q0 + rb + g;
#pragma unroll
        for (int nt = 0; nt < 8; nt++) {
            if (nt >= ntlim) break;
            int c0 = jb * 64 + nt * 8 + 2 * tg;
            sf[nt][0] = (c0     > row0)     ? NEG_INF : sf[nt][0] * sc;
            sf[nt][1] = (c0 + 1 > row0)     ? NEG_INF : sf[nt][1] * sc;
            sf[nt][2] = (c0     > row0 + 8) ? NEG_INF : sf[nt][2] * sc;
            sf[nt][3] = (c0 + 1 > row0 + 8) ? NEG_INF : sf[nt][3] * sc;
        }

        // row max (2 rows per thread), quad reduction
        float mx0 = NEG_INF, mx1 = NEG_INF;
#pragma unroll
        for (int nt = 0; nt < 8; nt++) {
            if (nt >= ntlim) break;
            mx0 = fmaxf(mx0, fmaxf(sf[nt][0], sf[nt][1]));
            mx1 = fmaxf(mx1, fmaxf(sf[nt][2], sf[nt][3]));
        }
        mx0 = fmaxf(mx0, __shfl_xor_sync(0xffffffffu, mx0, 1));
        mx0 = fmaxf(mx0, __shfl_xor_sync(0xffffffffu, mx0, 2));
        mx1 = fmaxf(mx1, __shfl_xor_sync(0xffffffffu, mx1, 1));
        mx1 = fmaxf(mx1, __shfl_xor_sync(0xffffffffu, mx1, 2));

        float mn0 = fmaxf(m0r, mx0), mn1 = fmaxf(m1r, mx1);
        float al0 = __expf(m0r - mn0), al1 = __expf(m1r - mn1);
        m0r = mn0; m1r = mn1;

        float s0 = 0.f, s1 = 0.f;
#pragma unroll
        for (int nt = 0; nt < 8; nt++) {
            if (nt >= ntlim) break;
            float p0 = __expf(sf[nt][0] - mn0); sf[nt][0] = p0; s0 += p0;
            float p1 = __expf(sf[nt][1] - mn0); sf[nt][1] = p1; s0 += p1;
            float p2 = __expf(sf[nt][2] - mn1); sf[nt][2] = p2; s1 += p2;
            float p3 = __expf(sf[nt][3] - mn1); sf[nt][3] = p3; s1 += p3;
        }
        s0 += __shfl_xor_sync(0xffffffffu, s0, 1);
        s0 += __shfl_xor_sync(0xffffffffu, s0, 2);
        s1 += __shfl_xor_sync(0xffffffffu, s1, 1);
        s1 += __shfl_xor_sync(0xffffffffu, s1, 2);
        l0r = l0r * al0 + s0;
        l1r = l1r * al1 + s1;
#pragma unroll
        for (int nt = 0; nt < 8; nt++) {
            o[nt][0] *= al0; o[nt][1] *= al0;
            o[nt][2] *= al1; o[nt][3] *= al1;
        }

        // P -> smem (tf32); each warp only touches its own 16 rows
#pragma unroll
        for (int nt = 0; nt < 8; nt++) {
            if (nt >= ntlim) break;
            int b0 = (rb + g) * 68 + nt * 8 + 2 * tg;
            Ps[b0]     = f2tf32(sf[nt][0]);
            Ps[b0 + 1] = f2tf32(sf[nt][1]);
            int b1 = (rb + g + 8) * 68 + nt * 8 + 2 * tg;
            Ps[b1]     = f2tf32(sf[nt][2]);
            Ps[b1 + 1] = f2tf32(sf[nt][3]);
        }
        __syncwarp();

        // O += P @ V   (only active k-groups of P)
#pragma unroll
        for (int kk = 0; kk < 8; kk++) {
            if (kk >= ntlim) break;
            uint32_t a[4];
            a[0] = Ps[(rb + g) * 68 + kk * 8 + tg];
            a[1] = Ps[(rb + g + 8) * 68 + kk * 8 + tg];
            a[2] = Ps[(rb + g) * 68 + kk * 8 + tg + 4];
            a[3] = Ps[(rb + g + 8) * 68 + kk * 8 + tg + 4];
#pragma unroll
            for (int nt = 0; nt < 8; nt++) {
                uint32_t b[2];
                b[0] = f2tf32(vb[(kk * 8 + tg) * 72 + nt * 8 + g]);
                b[1] = f2tf32(vb[(kk * 8 + tg + 4) * 72 + nt * 8 + g]);
                mma_tf32(o[nt], a, b);
            }
        }
    }

    // epilogue: normalize + store
    float inv0 = 1.0f / l0r, inv1 = 1.0f / l1r;
    const int r0 = q0 + rb + g;
#pragma unroll
    for (int nt = 0; nt < 8; nt++) {
        int cb = h * DH + nt * 8 + 2 * tg;
        *(float2*)&out[(size_t)r0 * DMODEL + cb] =
            make_float2(o[nt][0] * inv0, o[nt][1] * inv0);
        *(float2*)&out[(size_t)(r0 + 8) * DMODEL + cb] =
            make_float2(o[nt][2] * inv1, o[nt][3] * inv1);
    }
}

// ---------------------------------------------------------------------------
extern "C" void kernel_launch(void* const* d_in, const int* in_sizes, int n_in,
                              void* d_out, int out_size)
{
    const float* x     = (const float*)d_in[0];
    const float* w_in  = (const float*)d_in[1];
    const float* b_in  = (const float*)d_in[2];
    const float* w_out = (const float*)d_in[3];
    const float* b_out = (const float*)d_in[4];
    float* out = (float*)d_out;

    float *qkv = nullptr, *attn = nullptr;
    cudaGetSymbolAddress((void**)&qkv,  g_qkv);
    cudaGetSymbolAddress((void**)&attn, g_attn);

    const int gemm_smem = 4 * 128 * GSTR * (int)sizeof(float);                       // 73728
    const int attn_smem = (128 * 68 + 2 * 64 * 68 + 2 * 64 * 72) * (int)sizeof(float); // 106496
    cudaFuncSetAttribute(gemm_tf32,
                         cudaFuncAttributeMaxDynamicSharedMemorySize, gemm_smem);
    cudaFuncSetAttribute(attn_tf32,
                         cudaFuncAttributeMaxDynamicSharedMemorySize, attn_smem);

    dim3 blk(256);
    // QKV projection: [4096,2304] = x @ w_in^T + b_in
    gemm_tf32<<<dim3(QKV_LD / 128, S_LEN / 128), blk, gemm_smem>>>(
        x, w_in, b_in, qkv, QKV_LD);
    // Causal attention
    attn_tf32<<<dim3(S_LEN / 128, NH), blk, attn_smem>>>(qkv, attn);
    // Output projection: [4096,768] -> d_out
    gemm_tf32<<<dim3(DMODEL / 128, S_LEN / 128), blk, gemm_smem>>>(
        attn, w_out, b_out, out, DMODEL);
}

// round 7
// speedup vs baseline: 1.1300x; 1.1300x over previous
#include <cuda_runtime.h>
#include <cstdint>
#include <math.h>

#define S_LEN   4096
#define DMODEL  768
#define NH      12
#define DH      64
#define QKV_LD  2304   // 3 * DMODEL
#define KDIM    768    // contraction dim for both projections

#define NEG_INF (__int_as_float(0xff800000))

// Scratch (allocation-free rule: __device__ globals)
__device__ float g_qkv[(size_t)S_LEN * QKV_LD];    // [4096, 2304]
__device__ float g_attn[(size_t)S_LEN * DMODEL];   // [4096, 768]

// ---------------------------------------------------------------------------
// helpers
// ---------------------------------------------------------------------------
__device__ __forceinline__ uint32_t f2tf32(float f) {
    uint32_t r;
    asm("cvt.rna.tf32.f32 %0, %1;" : "=r"(r) : "f"(f));
    return r;
}

__device__ __forceinline__ void mma_tf32(float* d, const uint32_t* a, const uint32_t* b) {
    asm volatile(
        "mma.sync.aligned.m16n8k8.row.col.f32.tf32.tf32.f32 "
        "{%0,%1,%2,%3}, {%4,%5,%6,%7}, {%8,%9}, {%0,%1,%2,%3};"
        : "+f"(d[0]), "+f"(d[1]), "+f"(d[2]), "+f"(d[3])
        : "r"(a[0]), "r"(a[1]), "r"(a[2]), "r"(a[3]), "r"(b[0]), "r"(b[1]));
}

__device__ __forceinline__ void cp16(void* dst, const void* src) {
    uint32_t d = (uint32_t)__cvta_generic_to_shared(dst);
    asm volatile("cp.async.cg.shared.global [%0], [%1], 16;\n" :: "r"(d), "l"(src));
}
#define CP_COMMIT() asm volatile("cp.async.commit_group;\n" ::: "memory")
#define CP_WAIT0()  asm volatile("cp.async.wait_group 0;\n" ::: "memory")

// ---------------------------------------------------------------------------
// C[M,N] = A[M,768] @ B[N,768]^T + bias[N]   tf32 tensor-core GEMM
// CTA 128x128, 8 warps (2x4), warp 64x32, K-step 32, cp.async double buffer.
// smem fp32, stride 36 (==4 mod 32) -> conflict-free fragment loads.
// (unchanged from R5: 123 us, tensor=44%)
// ---------------------------------------------------------------------------
#define GSTR 36
#define KT_N (KDIM / 32)   // 24

__global__ __launch_bounds__(256, 2) void gemm_tf32(
    const float* __restrict__ A, const float* __restrict__ B,
    const float* __restrict__ bias, float* __restrict__ C, int N)
{
    extern __shared__ float smg[];
    float* As = smg;                   // [2][128*GSTR]
    float* Bs = smg + 2 * 128 * GSTR;  // [2][128*GSTR]

    const int t = threadIdx.x, lane = t & 31;
    const int w = t >> 5, wm = w >> 2, wn = w & 3;
    const int g = lane >> 2, tg = lane & 3;
    const int m0 = blockIdx.y * 128, n0 = blockIdx.x * 128;

    const int lrow = t >> 3, lc = (t & 7) * 4;  // 8 threads per 32-col row

    float acc[4][4][4] = {};

    // prologue: issue k-tile 0
#pragma unroll
    for (int i = 0; i < 4; i++) {
        int row = lrow + i * 32;
        cp16(&As[row * GSTR + lc], &A[(size_t)(m0 + row) * KDIM + lc]);
        cp16(&Bs[row * GSTR + lc], &B[(size_t)(n0 + row) * KDIM + lc]);
    }
    CP_COMMIT();

    for (int kt = 0; kt < KT_N; kt++) {
        CP_WAIT0();
        __syncthreads();
        if (kt + 1 < KT_N) {
            float* an = As + ((kt + 1) & 1) * 128 * GSTR;
            float* bn = Bs + ((kt + 1) & 1) * 128 * GSTR;
            const int ko = (kt + 1) * 32 + lc;
#pragma unroll
            for (int i = 0; i < 4; i++) {
                int row = lrow + i * 32;
                cp16(&an[row * GSTR + lc], &A[(size_t)(m0 + row) * KDIM + ko]);
                cp16(&bn[row * GSTR + lc], &B[(size_t)(n0 + row) * KDIM + ko]);
            }
            CP_COMMIT();
        }
        const float* ab = As + (kt & 1) * 128 * GSTR;
        const float* bb = Bs + (kt & 1) * 128 * GSTR;
#pragma unroll
        for (int kk = 0; kk < 4; kk++) {
            uint32_t afr[4][4], bfr[4][2];
#pragma unroll
            for (int mt = 0; mt < 4; mt++) {
                int r = wm * 64 + mt * 16 + g;
                afr[mt][0] = f2tf32(ab[r * GSTR + kk * 8 + tg]);
                afr[mt][1] = f2tf32(ab[(r + 8) * GSTR + kk * 8 + tg]);
                afr[mt][2] = f2tf32(ab[r * GSTR + kk * 8 + tg + 4]);
                afr[mt][3] = f2tf32(ab[(r + 8) * GSTR + kk * 8 + tg + 4]);
            }
#pragma unroll
            for (int nt = 0; nt < 4; nt++) {
                int c = wn * 32 + nt * 8 + g;
                bfr[nt][0] = f2tf32(bb[c * GSTR + kk * 8 + tg]);
                bfr[nt][1] = f2tf32(bb[c * GSTR + kk * 8 + tg + 4]);
            }
#pragma unroll
            for (int mt = 0; mt < 4; mt++)
#pragma unroll
                for (int nt = 0; nt < 4; nt++)
                    mma_tf32(acc[mt][nt], afr[mt], bfr[nt]);
        }
    }

    // epilogue: bias + store
#pragma unroll
    for (int nt = 0; nt < 4; nt++) {
        int cb = n0 + wn * 32 + nt * 8 + 2 * tg;
        float2 bv = *(const float2*)&bias[cb];
#pragma unroll
        for (int mt = 0; mt < 4; mt++) {
            int r = m0 + wm * 64 + mt * 16 + g;
            *(float2*)&C[(size_t)r * N + cb] =
                make_float2(acc[mt][nt][0] + bv.x, acc[mt][nt][1] + bv.y);
            *(float2*)&C[(size_t)(r + 8) * N + cb] =
                make_float2(acc[mt][nt][2] + bv.x, acc[mt][nt][3] + bv.y);
        }
    }
}

// ---------------------------------------------------------------------------
// Causal flash attention, tf32 tensor cores.
// cp.async double-buffered raw-fp32 K/V + one in-place fp32->tf32 convert
// pass per tile (converted ONCE, then all fragment loads are plain LDS).
// One CTA = (head, 128-row q tile). 8 warps, 16 q rows each. Bc=64.
// Q fragments in registers. Warp-level causal skipping (ntlim).
// smem: Ps[128*68] + K[2][64*68] + V[2][64*72] = 106,496 B.
// ---------------------------------------------------------------------------
__global__ __launch_bounds__(256, 2) void attn_tf32(
    const float* __restrict__ qkv, float* __restrict__ out)
{
    extern __shared__ uint32_t sma[];
    uint32_t* Ps = sma;                   // [128][68] tf32 (Q staging first)
    uint32_t* Ks = sma + 128 * 68;        // [2][64][68] fp32 -> tf32 in place
    uint32_t* Vs = Ks + 2 * 64 * 68;      // [2][64][72]

    const int qb = (int)(gridDim.x - 1) - (int)blockIdx.x;  // heavy tiles first
    const int h = blockIdx.y;
    const int q0 = qb * 128;
    const int t = threadIdx.x, lane = t & 31, w = t >> 5;
    const int g = lane >> 2, tg = lane & 3;
    const int rb = w * 16;

    const int lrow = t >> 4, lc = (t & 15) * 4;  // 16 threads per 64-col row
    const int jbmax = 2 * qb + 1;

    // prologue: issue raw K/V for jb=0
#pragma unroll
    for (int i = 0; i < 4; i++) {
        int row = lrow + i * 16;
        const float* bp = &qkv[(size_t)row * QKV_LD + h * DH + lc];
        cp16(&Ks[row * 68 + lc], bp + DMODEL);
        cp16(&Vs[row * 72 + lc], bp + 2 * DMODEL);
    }
    CP_COMMIT();

    // stage Q (fp32) via Ps region, then extract per-warp a-fragments to regs
    {
        float* Pf = (float*)Ps;
#pragma unroll
        for (int i = 0; i < 8; i++) {
            int row = lrow + i * 16;
            *(float4*)&Pf[row * 68 + lc] =
                *(const float4*)&qkv[(size_t)(q0 + row) * QKV_LD + h * DH + lc];
        }
    }
    __syncthreads();
    uint32_t qa[8][4];
    {
        const float* Pf = (const float*)Ps;
#pragma unroll
        for (int d8 = 0; d8 < 8; d8++) {
            qa[d8][0] = f2tf32(Pf[(rb + g) * 68 + d8 * 8 + tg]);
            qa[d8][1] = f2tf32(Pf[(rb + g + 8) * 68 + d8 * 8 + tg]);
            qa[d8][2] = f2tf32(Pf[(rb + g) * 68 + d8 * 8 + tg + 4]);
            qa[d8][3] = f2tf32(Pf[(rb + g + 8) * 68 + d8 * 8 + tg + 4]);
        }
    }

    float o[8][4] = {};
    float m0r = NEG_INF, m1r = NEG_INF;
    float l0r = 0.f, l1r = 0.f;
    const float sc = 0.125f;  // 1/sqrt(64)

    for (int jb = 0; jb <= jbmax; jb++) {
        CP_WAIT0();
        __syncthreads();   // tile jb landed; all compute on other buffer done

        // prefetch jb+1 into the other buffer (safe: its last reader was jb-1)
        if (jb < jbmax) {
            uint32_t* kn = Ks + ((jb + 1) & 1) * 64 * 68;
            uint32_t* vn = Vs + ((jb + 1) & 1) * 64 * 72;
#pragma unroll
            for (int i = 0; i < 4; i++) {
                int row = lrow + i * 16;
                const float* bp = &qkv[(size_t)((jb + 1) * 64 + row) * QKV_LD + h * DH + lc];
                cp16(&kn[row * 68 + lc], bp + DMODEL);
                cp16(&vn[row * 72 + lc], bp + 2 * DMODEL);
            }
            CP_COMMIT();
        }

        uint32_t* kb = Ks + (jb & 1) * 64 * 68;
        uint32_t* vb = Vs + (jb & 1) * 64 * 72;

        // in-place fp32 -> tf32 convert (once per tile, whole CTA)
#pragma unroll
        for (int i = 0; i < 4; i++) {
            int row = lrow + i * 16;
            float4 kv = *(const float4*)&kb[row * 68 + lc];
            *(uint4*)&kb[row * 68 + lc] =
                make_uint4(f2tf32(kv.x), f2tf32(kv.y), f2tf32(kv.z), f2tf32(kv.w));
            float4 vv = *(const float4*)&vb[row * 72 + lc];
            *(uint4*)&vb[row * 72 + lc] =
                make_uint4(f2tf32(vv.x), f2tf32(vv.y), f2tf32(vv.z), f2tf32(vv.w));
        }
        __syncthreads();

        // warp-level causal limit: active 8-col groups in this k-tile
        const int cmax = q0 + rb + 15 - jb * 64;
        if (cmax < 0) continue;                       // warp fully above diagonal
        const int ntlim = cmax >= 63 ? 8 : ((cmax >> 3) + 1);

        // S = Q @ K^T
        float sf[8][4] = {};
#pragma unroll
        for (int d8 = 0; d8 < 8; d8++) {
#pragma unroll
            for (int nt = 0; nt < 8; nt++) {
                if (nt >= ntlim) break;
                uint32_t b[2];
                b[0] = kb[(nt * 8 + g) * 68 + d8 * 8 + tg];
                b[1] = kb[(nt * 8 + g) * 68 + d8 * 8 + tg + 4];
                mma_tf32(sf[nt], qa[d8], b);
            }
        }

        // scale + causal mask
        const int row0 = q0 + rb + g;
#pragma unroll
        for (int nt = 0; nt < 8; nt++) {
            if (nt >= ntlim) break;
            int c0 = jb * 64 + nt * 8 + 2 * tg;
            sf[nt][0] = (c0     > row0)     ? NEG_INF : sf[nt][0] * sc;
            sf[nt][1] = (c0 + 1 > row0)     ? NEG_INF : sf[nt][1] * sc;
            sf[nt][2] = (c0     > row0 + 8) ? NEG_INF : sf[nt][2] * sc;
            sf[nt][3] = (c0 + 1 > row0 + 8) ? NEG_INF : sf[nt][3] * sc;
        }

        // row max (2 rows per thread), quad reduction
        float mx0 = NEG_INF, mx1 = NEG_INF;
#pragma unroll
        for (int nt = 0; nt < 8; nt++) {
            if (nt >= ntlim) break;
            mx0 = fmaxf(mx0, fmaxf(sf[nt][0], sf[nt][1]));
            mx1 = fmaxf(mx1, fmaxf(sf[nt][2], sf[nt][3]));
        }
        mx0 = fmaxf(mx0, __shfl_xor_sync(0xffffffffu, mx0, 1));
        mx0 = fmaxf(mx0, __shfl_xor_sync(0xffffffffu, mx0, 2));
        mx1 = fmaxf(mx1, __shfl_xor_sync(0xffffffffu, mx1, 1));
        mx1 = fmaxf(mx1, __shfl_xor_sync(0xffffffffu, mx1, 2));

        float mn0 = fmaxf(m0r, mx0), mn1 = fmaxf(m1r, mx1);
        float al0 = __expf(m0r - mn0), al1 = __expf(m1r - mn1);
        m0r = mn0; m1r = mn1;

        float s0 = 0.f, s1 = 0.f;
#pragma unroll
        for (int nt = 0; nt < 8; nt++) {
            if (nt >= ntlim) break;
            float p0 = __expf(sf[nt][0] - mn0); sf[nt][0] = p0; s0 += p0;
            float p1 = __expf(sf[nt][1] - mn0); sf[nt][1] = p1; s0 += p1;
            float p2 = __expf(sf[nt][2] - mn1); sf[nt][2] = p2; s1 += p2;
            float p3 = __expf(sf[nt][3] - mn1); sf[nt][3] = p3; s1 += p3;
        }
        s0 += __shfl_xor_sync(0xffffffffu, s0, 1);
        s0 += __shfl_xor_sync(0xffffffffu, s0, 2);
        s1 += __shfl_xor_sync(0xffffffffu, s1, 1);
        s1 += __shfl_xor_sync(0xffffffffu, s1, 2);
        l0r = l0r * al0 + s0;
        l1r = l1r * al1 + s1;
#pragma unroll
        for (int nt = 0; nt < 8; nt++) {
            o[nt][0] *= al0; o[nt][1] *= al0;
            o[nt][2] *= al1; o[nt][3] *= al1;
        }

        // P -> smem (tf32); each warp only touches its own 16 rows
#pragma unroll
        for (int nt = 0; nt < 8; nt++) {
            if (nt >= ntlim) break;
            int b0 = (rb + g) * 68 + nt * 8 + 2 * tg;
            Ps[b0]     = f2tf32(sf[nt][0]);
            Ps[b0 + 1] = f2tf32(sf[nt][1]);
            int b1 = (rb + g + 8) * 68 + nt * 8 + 2 * tg;
            Ps[b1]     = f2tf32(sf[nt][2]);
            Ps[b1 + 1] = f2tf32(sf[nt][3]);
        }
        __syncwarp();

        // O += P @ V   (only active k-groups of P)
#pragma unroll
        for (int kk = 0; kk < 8; kk++) {
            if (kk >= ntlim) break;
            uint32_t a[4];
            a[0] = Ps[(rb + g) * 68 + kk * 8 + tg];
            a[1] = Ps[(rb + g + 8) * 68 + kk * 8 + tg];
            a[2] = Ps[(rb + g) * 68 + kk * 8 + tg + 4];
            a[3] = Ps[(rb + g + 8) * 68 + kk * 8 + tg + 4];
#pragma unroll
            for (int nt = 0; nt < 8; nt++) {
                uint32_t b[2];
                b[0] = vb[(kk * 8 + tg) * 72 + nt * 8 + g];
                b[1] = vb[(kk * 8 + tg + 4) * 72 + nt * 8 + g];
                mma_tf32(o[nt], a, b);
            }
        }
    }

    // epilogue: normalize + store
    float inv0 = 1.0f / l0r, inv1 = 1.0f / l1r;
    const int r0 = q0 + rb + g;
#pragma unroll
    for (int nt = 0; nt < 8; nt++) {
        int cb = h * DH + nt * 8 + 2 * tg;
        *(float2*)&out[(size_t)r0 * DMODEL + cb] =
            make_float2(o[nt][0] * inv0, o[nt][1] * inv0);
        *(float2*)&out[(size_t)(r0 + 8) * DMODEL + cb] =
            make_float2(o[nt][2] * inv1, o[nt][3] * inv1);
    }
}

// ---------------------------------------------------------------------------
extern "C" void kernel_launch(void* const* d_in, const int* in_sizes, int n_in,
                              void* d_out, int out_size)
{
    const float* x     = (const float*)d_in[0];
    const float* w_in  = (const float*)d_in[1];
    const float* b_in  = (const float*)d_in[2];
    const float* w_out = (const float*)d_in[3];
    const float* b_out = (const float*)d_in[4];
    float* out = (float*)d_out;

    float *qkv = nullptr, *attn = nullptr;
    cudaGetSymbolAddress((void**)&qkv,  g_qkv);
    cudaGetSymbolAddress((void**)&attn, g_attn);

    const int gemm_smem = 4 * 128 * GSTR * (int)sizeof(float);                         // 73728
    const int attn_smem = (128 * 68 + 2 * 64 * 68 + 2 * 64 * 72) * (int)sizeof(float); // 106496
    cudaFuncSetAttribute(gemm_tf32,
                         cudaFuncAttributeMaxDynamicSharedMemorySize, gemm_smem);
    cudaFuncSetAttribute(attn_tf32,
                         cudaFuncAttributeMaxDynamicSharedMemorySize, attn_smem);

    dim3 blk(256);
    // QKV projection: [4096,2304] = x @ w_in^T + b_in
    gemm_tf32<<<dim3(QKV_LD / 128, S_LEN / 128), blk, gemm_smem>>>(
        x, w_in, b_in, qkv, QKV_LD);
    // Causal attention
    attn_tf32<<<dim3(S_LEN / 128, NH), blk, attn_smem>>>(qkv, attn);
    // Output projection: [4096,768] -> d_out
    gemm_tf32<<<dim3(DMODEL / 128, S_LEN / 128), blk, gemm_smem>>>(
        attn, w_out, b_out, out, DMODEL);
}